// round 16
// baseline (speedup 1.0000x reference)
#include <cuda_runtime.h>
#include <cuda_bf16.h>

#define NROWS  8192
#define DIM    1024
#define NPAIRS 1024
#define SLOTS  32            // fixed bin capacity; P(overflow) ~ 1e-8 (Poisson 8)
#define MARGIN_RANK 0.05f
#define FULL   0xFFFFFFFFu

// ---------------- device scratch (no allocations allowed) ----------------
__device__ float  g_sp[NROWS];             // raw row-normalized sims (fallback)
__device__ float  g_sn[NROWS];
__device__ int    g_bcnt[NPAIRS];          // counts; read+reset by K2 each launch
__device__ float4 g_slot[NPAIRS * SLOTS];  // direct-addressed bins {sp, sn, lev, 0}
__device__ float  g_cons_sum, g_pos_sum, g_neg_sum;
__device__ int    g_cons_cnt, g_rank_cnt;
__device__ int    g_done;

// ---------------- K1: pure GEMV + direct-bin scatter (R12-proven) ---------
// 1024 blocks x 256 threads, one warp per row. Row loads issued first;
// lane 0 takes a bucket ticket and stores the raw record into its bin.
__global__ void __launch_bounds__(256) K1_gemv(
    const float4* __restrict__ x, const float4* __restrict__ tp4,
    const float4* __restrict__ tn4, const int* __restrict__ pair,
    const int* __restrict__ lev)
{
    int t = threadIdx.x, lane = t & 31, w = t >> 5;
    int row = blockIdx.x * 8 + w;

    int p = 0, lv = 0;
    if (lane == 0) { p = pair[row]; lv = lev[row]; }   // in flight early

    const float4* r4 = x + (size_t)row * (DIM / 4);
    float4 v[8];
    #pragma unroll
    for (int k = 0; k < 8; k++) v[k] = r4[k * 32 + lane];   // 8 loads in flight

    float dp = 0.f, dn = 0.f, dx = 0.f;
    #pragma unroll
    for (int k = 0; k < 8; k++) {
        float4 pt = __ldg(tp4 + k * 32 + lane);
        float4 qt = __ldg(tn4 + k * 32 + lane);
        dp += v[k].x*pt.x + v[k].y*pt.y + v[k].z*pt.z + v[k].w*pt.w;
        dn += v[k].x*qt.x + v[k].y*qt.y + v[k].z*qt.z + v[k].w*qt.w;
        dx += v[k].x*v[k].x + v[k].y*v[k].y + v[k].z*v[k].z + v[k].w*v[k].w;
    }
    #pragma unroll
    for (int o = 16; o; o >>= 1) {
        dp += __shfl_xor_sync(FULL, dp, o);
        dn += __shfl_xor_sync(FULL, dn, o);
        dx += __shfl_xor_sync(FULL, dx, o);
    }
    if (lane == 0) {
        float inv = rsqrtf(dx);
        float sp = dp * inv, sn = dn * inv;     // raw (text norm applied in K2)
        g_sp[row] = sp;                          // overflow-fallback copy
        g_sn[row] = sn;
        int rank = atomicAdd(&g_bcnt[p], 1);
        if (rank < SLOTS) {
            float4 o4;
            o4.x = sp; o4.y = sn; o4.z = __int_as_float(lv); o4.w = 0.f;
            g_slot[p * SLOTS + rank] = o4;
        }
    }
}

// ---------------- K2: PDL-overlapped pairs kernel --------------------------
// Launched with programmatic stream serialization: blocks start WHILE K1
// runs. Prelude (launch ramp + text inverse-norms from inputs only) executes
// in the overlap window; cudaGridDependencySynchronize() then waits for K1
// completion (implicit end-of-kernel trigger => full visibility) before any
// read of K1's outputs.
__global__ void __launch_bounds__(256) K2_pairs(
    const float* __restrict__ tp, const float* __restrict__ tn,
    const int* __restrict__ pair, const int* __restrict__ lev,
    float* __restrict__ out)
{
    __shared__ float sA[8], sB[8];
    __shared__ float sinv[2];

    int t = threadIdx.x, lane = t & 31, w = t >> 5;

    // ---- prelude: independent of K1 (inputs only) ----
    float pa = 0.f, pb = 0.f;
    #pragma unroll
    for (int j = 0; j < 4; j++) {
        float a = tp[t + j * 256], b = tn[t + j * 256];
        pa += a * a;  pb += b * b;
    }
    #pragma unroll
    for (int o = 16; o; o >>= 1) {
        pa += __shfl_xor_sync(FULL, pa, o);
        pb += __shfl_xor_sync(FULL, pb, o);
    }
    if (lane == 0) { sA[w] = pa; sB[w] = pb; }
    __syncthreads();
    if (t == 0) {
        float qa = 0.f, qb = 0.f;
        #pragma unroll
        for (int j = 0; j < 8; j++) { qa += sA[j]; qb += sB[j]; }
        sinv[0] = rsqrtf(qa);
        sinv[1] = rsqrtf(qb);
    }
    __syncthreads();
    float invp = sinv[0], invn = sinv[1];

    // ---- wait for K1 (PDL dependency) ----
#if __CUDA_ARCH__ >= 900
    cudaGridDependencySynchronize();
#endif

    int wg = blockIdx.x * 8 + w;
    int c = 0;
    if (lane == 0) { c = g_bcnt[wg]; g_bcnt[wg] = 0; }   // read then reset
    c = __shfl_sync(FULL, c, 0);

    float cs = 0.f, ps = 0.f, ns = 0.f;
    int cc = 0, rc = 0;

    if (c <= SLOTS) {
        float sp = 0.f, sn = 0.f; int lv = 0;
        bool act = lane < c;
        if (act) {
            float4 va = g_slot[wg * SLOTS + lane];       // coalesced 512B
            sp = va.x * invp; sn = va.y * invn; lv = __float_as_int(va.z);
        }
        for (int b = 0; b < c; b++) {
            float spb = __shfl_sync(FULL, sp, b);
            float snb = __shfl_sync(FULL, sn, b);
            int   lb  = __shfl_sync(FULL, lv, b);
            if (act && lv == lb && lane < b) {
                cs += fabsf(sp - spb) + fabsf(sn - snb);
                cc++;
            }
            if (act && lv < lb) {
                ps += fmaxf(MARGIN_RANK - (sp - spb), 0.f);
                ns += fmaxf(MARGIN_RANK + (sn - snb), 0.f);
                rc++;
            }
        }
    } else {
        // astronomically-unlikely overflow: correct-but-slow row scan
        for (int i = lane; i < NROWS; i += 32) {
            if (pair[i] != wg) continue;
            float spa = g_sp[i] * invp, sna = g_sn[i] * invn;
            int   la  = lev[i];
            for (int j = 0; j < NROWS; j++) {
                if (pair[j] != wg) continue;
                float spb = g_sp[j] * invp, snb = g_sn[j] * invn;
                int   lb  = lev[j];
                if (la == lb && i < j) {
                    cs += fabsf(spa - spb) + fabsf(sna - snb);
                    cc++;
                }
                if (la < lb) {
                    ps += fmaxf(MARGIN_RANK - (spa - spb), 0.f);
                    ns += fmaxf(MARGIN_RANK + (sna - snb), 0.f);
                    rc++;
                }
            }
        }
    }

    #pragma unroll
    for (int o = 16; o; o >>= 1) {
        cs += __shfl_xor_sync(FULL, cs, o);
        ps += __shfl_xor_sync(FULL, ps, o);
        ns += __shfl_xor_sync(FULL, ns, o);
        cc += __shfl_xor_sync(FULL, cc, o);
        rc += __shfl_xor_sync(FULL, rc, o);
    }
    if (lane == 0 && (cc | rc)) {
        atomicAdd(&g_cons_sum, cs);
        atomicAdd(&g_pos_sum,  ps);
        atomicAdd(&g_neg_sum,  ns);
        atomicAdd(&g_cons_cnt, cc);
        atomicAdd(&g_rank_cnt, rc);
    }

    // fused finalize: last block writes the scalar + resets state for replay
    __syncthreads();
    if (t == 0) {
        __threadfence();
        if (atomicAdd(&g_done, 1) == (int)gridDim.x - 1) {
            __threadfence();
            float lc = (g_cons_cnt > 0) ? g_cons_sum / (float)(2 * g_cons_cnt) : 0.f;
            float lp = (g_rank_cnt > 0) ? g_pos_sum  / (float)g_rank_cnt       : 0.f;
            float ln = (g_rank_cnt > 0) ? g_neg_sum  / (float)g_rank_cnt       : 0.f;
            out[0] = lc + lp + ln;
            g_cons_sum = 0.f; g_pos_sum = 0.f; g_neg_sum = 0.f;
            g_cons_cnt = 0;   g_rank_cnt = 0;  g_done = 0;
        }
    }
}

// ---------------- launch ---------------------------------------------------
extern "C" void kernel_launch(void* const* d_in, const int* in_sizes, int n_in,
                              void* d_out, int out_size) {
    const float* img  = (const float*)d_in[0];  // [8192, 1024]
    const float* tp   = (const float*)d_in[1];  // [1024]
    const float* tn   = (const float*)d_in[2];  // [1024]
    const int*   lev  = (const int*)  d_in[3];  // [8192]
    const int*   pair = (const int*)  d_in[4];  // [8192]
    float* out = (float*)d_out;

    K1_gemv<<<NROWS / 8, 256>>>(
        (const float4*)img, (const float4*)tp, (const float4*)tn, pair, lev);

    // K2 with programmatic dependent launch: overlap its startup with K1
    cudaLaunchConfig_t cfg = {};
    cfg.gridDim  = dim3(NPAIRS / 8, 1, 1);
    cfg.blockDim = dim3(256, 1, 1);
    cfg.dynamicSmemBytes = 0;
    cfg.stream = 0;                            // legacy stream (same as <<<>>>)
    cudaLaunchAttribute attrs[1];
    attrs[0].id = cudaLaunchAttributeProgrammaticStreamSerialization;
    attrs[0].val.programmaticStreamSerializationAllowed = 1;
    cfg.attrs = attrs;
    cfg.numAttrs = 1;
    cudaLaunchKernelEx(&cfg, K2_pairs, tp, tn, pair, lev, out);
}